// round 6
// baseline (speedup 1.0000x reference)
#include <cuda_runtime.h>

// ---------------------------------------------------------------------------
// NCA step:  p = depthwise [ident, sobel_x, sobel_y] (16ch -> 48ch)
//            h = relu(W1 p + b1)   (48 -> 128)
//            dx = W2 h             (128 -> 16)
//            x_new = x + dx * update_mask
//            out   = x_new * (maxpool3(x[3])>0.1 & maxpool3(x_new[3])>0.1)
// ---------------------------------------------------------------------------

#define Bn  32
#define Cn  16
#define Hn  256
#define Wn  256
#define HCH 128
#define THRESH 0.1f

// 134 MB scratch for x_new (device global: allocation-free rule)
__device__ float g_xnew[Bn * Cn * Hn * Wn];

typedef unsigned long long u64;

__device__ __forceinline__ u64 fma2(u64 a, u64 b, u64 c) {
    u64 d; asm("fma.rn.f32x2 %0, %1, %2, %3;" : "=l"(d) : "l"(a), "l"(b), "l"(c)); return d;
}
__device__ __forceinline__ u64 add2(u64 a, u64 b) {
    u64 d; asm("add.rn.f32x2 %0, %1, %2;" : "=l"(d) : "l"(a), "l"(b)); return d;
}
__device__ __forceinline__ u64 sub2(u64 a, u64 b) {
    u64 d; asm("sub.rn.f32x2 %0, %1, %2;" : "=l"(d) : "l"(a), "l"(b)); return d;
}
__device__ __forceinline__ u64 mul2(u64 a, u64 b) {
    u64 d; asm("mul.rn.f32x2 %0, %1, %2;" : "=l"(d) : "l"(a), "l"(b)); return d;
}
__device__ __forceinline__ u64 pack2(float lo, float hi) {
    u64 d; asm("mov.b64 %0, {%1, %2};" : "=l"(d) : "f"(lo), "f"(hi)); return d;
}
__device__ __forceinline__ void unpack2(u64 v, float& lo, float& hi) {
    asm("mov.b64 {%0, %1}, %2;" : "=f"(lo), "=f"(hi) : "l"(v));
}
__device__ __forceinline__ float lo2(u64 v) { float a, b; unpack2(v, a, b); return a; }
__device__ __forceinline__ float hi2(u64 v) { float a, b; unpack2(v, a, b); return b; }

// one LDS.128 -> two ready u64 (duplicated-pair) operands, no repacking
__device__ __forceinline__ void lds2x64(u64& a, u64& b, unsigned int addr) {
    asm("ld.shared.v2.u64 {%0, %1}, [%2];" : "=l"(a), "=l"(b) : "r"(addr));
}
__device__ __forceinline__ u64 lds64(unsigned int addr) {
    u64 a; asm("ld.shared.b64 %0, [%1];" : "=l"(a) : "r"(addr)); return a;
}

// ---------------------------------------------------------------------------
// Kernel 1: perception + MLP + masked residual update -> g_xnew
// block (16,8) = 128 threads, 2 horizontally adjacent pixels per thread.
// Smem phases (overlaid):
//   phase A: xs = x tile + halo (16ch x 10r x 36c floats, 23 KB)
//   phase B: weights duplicated {w,w}:
//     w1d [128][48] u64 (49152 B) | w2t [128][16] u64 (16384 B) | b1 (1024 B)
// Total 66560 B -> 3 CTAs/SM.  Registers kept under the 170 cap (no spills):
// p[48]+acc[16] pairs = 128 regs, inner loop uses only 4 u64 load temps.
// ---------------------------------------------------------------------------
extern __shared__ unsigned char smem_raw[];

__global__ void __launch_bounds__(128, 3)
nca_update(const float* __restrict__ x,
           const float* __restrict__ w1,
           const float* __restrict__ b1,
           const float* __restrict__ w2,
           const unsigned int* __restrict__ um)   // mask: 32-bit words, nonzero == true
{
    const int tid = threadIdx.y * 16 + threadIdx.x;
    const int b  = blockIdx.z;
    const int y0 = blockIdx.y * 8;
    const int x0 = blockIdx.x * 32;

    // ---- phase A: x tile + 1-halo into xs (overlaid on weight region) ----
    float* xs = (float*)smem_raw;   // [16][10][36], col j <-> global col x0-1+j
    const float* xb = x + ((long long)b * Cn << 16);
    for (int i = tid; i < 16 * 10 * 34; i += 128) {
        int c   = i / 340;
        int rem = i - c * 340;
        int r   = rem / 34;
        int col = rem - r * 34;
        int gy = y0 - 1 + r;
        int gx = x0 - 1 + col;
        float v = 0.0f;                              // 'SAME' zero padding for conv
        if ((unsigned)gy < Hn && (unsigned)gx < Wn)
            v = xb[(c << 16) + (gy << 8) + gx];
        xs[c * 360 + r * 36 + col] = v;
    }
    __syncthreads();

    const int ly = threadIdx.y;   // 0..7
    const int tx = threadIdx.x;   // 0..15; pixels gxA = x0+2tx, gxB = gxA+1

    // ---- perception with aligned LDS.64 + f32x2 sobel ----
    const u64 c0125 = pack2(0.125f, 0.125f);
    const u64 c025  = pack2(0.25f, 0.25f);
    u64 p[48];
#pragma unroll
    for (int c = 0; c < 16; ++c) {
        const u64* row0 = (const u64*)(xs + c * 360 + (ly + 0) * 36) + tx;
        const u64* row1 = (const u64*)(xs + c * 360 + (ly + 1) * 36) + tx;
        const u64* row2 = (const u64*)(xs + c * 360 + (ly + 2) * 36) + tx;
        u64 a0 = row0[0], b0 = row0[1];
        u64 a1 = row1[0], b1v = row1[1];
        u64 a2 = row2[0], b2 = row2[1];
        u64 r0 = sub2(b0, a0);
        u64 r1 = sub2(b1v, a1);
        u64 r2 = sub2(b2, a2);
        u64 sx = fma2(r1, c025, mul2(add2(r0, r2), c0125));
        u64 da = sub2(a2, a0);
        u64 db = sub2(b2, b0);
        u64 mid = pack2(hi2(da), lo2(db));
        u64 sy = fma2(mid, c025, mul2(add2(da, db), c0125));
        p[3 * c + 0] = pack2(hi2(a1), lo2(b1v));   // ident = x at {gxA, gxB}
        p[3 * c + 1] = sx;
        p[3 * c + 2] = sy;
    }
    __syncthreads();   // xs dead; safe to overwrite with weights

    // ---- phase B: stage duplicated weights into smem ----
    float4* w1f4 = (float4*)smem_raw;                          // [128][24] float4 view
    float2* w2t  = (float2*)(smem_raw + 49152);                // [128][16] {w,w}
    float2* b1d  = (float2*)(smem_raw + 65536);                // [128]

    const float4* w1g = (const float4*)w1;   // 6144 floats = 1536 float4
    for (int i = tid; i < 1536; i += 128) {
        float4 v = w1g[i];
        w1f4[2 * i]     = make_float4(v.x, v.x, v.y, v.y);
        w1f4[2 * i + 1] = make_float4(v.z, v.z, v.w, v.w);
    }
    for (int i = tid; i < 2048; i += 128) {
        int o = i >> 4, k = i & 15;
        float v = w2[k * HCH + o];
        w2t[i] = make_float2(v, v);
    }
    if (tid < HCH) { float v = b1[tid]; b1d[tid] = make_float2(v, v); }
    __syncthreads();

    // mask load early (hide latency behind MLP)
    const int gy    = y0 + ly;
    const int gxA   = x0 + 2 * tx;
    const uint2 mv  = *(const uint2*)(um + ((b << 16) + (gy << 8) + gxA));
    const u64 mm = pack2(mv.x ? 1.0f : 0.0f, mv.y ? 1.0f : 0.0f);

    // shared-space base addresses for raw LDS
    const unsigned int sbase = (unsigned int)__cvta_generic_to_shared(smem_raw);
    const unsigned int w2base = sbase + 49152;
    const unsigned int b1base = sbase + 65536;

    // ---- fused MLP ----
    u64 acc[16];
#pragma unroll
    for (int k = 0; k < 16; ++k) acc[k] = 0ull;

#pragma unroll 1
    for (int o = 0; o < HCH; ++o) {
        const unsigned int w1o = sbase + o * 384;     // 48 u64 per row
        u64 h0 = lds64(b1base + o * 8);
        u64 h1 = 0ull, h2 = 0ull, h3 = 0ull;
#pragma unroll
        for (int i = 0; i < 12; ++i) {                // 24 x LDS.128 -> 48 u64
            u64 wa, wb, wc, wd;
            lds2x64(wa, wb, w1o + i * 32);
            lds2x64(wc, wd, w1o + i * 32 + 16);
            h0 = fma2(wa, p[4 * i + 0], h0);
            h1 = fma2(wb, p[4 * i + 1], h1);
            h2 = fma2(wc, p[4 * i + 2], h2);
            h3 = fma2(wd, p[4 * i + 3], h3);
        }
        u64 h = add2(add2(h0, h1), add2(h2, h3));
        float lo, hi;
        unpack2(h, lo, hi);
        h = pack2(fmaxf(lo, 0.0f), fmaxf(hi, 0.0f));

        const unsigned int w2o = w2base + o * 128;    // 16 u64 per row
#pragma unroll
        for (int k4 = 0; k4 < 8; ++k4) {              // 8 x LDS.128 -> 16 u64
            u64 wa, wb;
            lds2x64(wa, wb, w2o + k4 * 16);
            acc[2 * k4 + 0] = fma2(wa, h, acc[2 * k4 + 0]);
            acc[2 * k4 + 1] = fma2(wb, h, acc[2 * k4 + 1]);
        }
    }

    // ---- epilogue: x_new = x + dx*mask -> g_xnew (x values live in p[3c]) ----
#pragma unroll
    for (int k = 0; k < 16; ++k) {
        u64 xn = fma2(acc[k], mm, p[3 * k]);
        float lo, hi;
        unpack2(xn, lo, hi);
        *(float2*)(g_xnew + (((b * Cn + k) << 16) + (gy << 8) + gxA)) = make_float2(lo, hi);
    }
}

// ---------------------------------------------------------------------------
// Kernel 2: alive gating.  out = x_new * (maxpool3(x[3])>thr & maxpool3(x_new[3])>thr)
// block (32,8), tile 128x8, 4 px/thread via float4; column-max reuse.
// ---------------------------------------------------------------------------
__global__ void __launch_bounds__(256)
nca_mask(const float* __restrict__ x, float* __restrict__ out)
{
    __shared__ float s3[10][136];
    __shared__ float sn3[10][136];

    const int b  = blockIdx.z;
    const int y0 = blockIdx.y * 8;
    const int x0 = blockIdx.x * 128;
    const int tid = threadIdx.y * 32 + threadIdx.x;
    const int plane = ((b * Cn + 3) << 16);

    for (int i = tid; i < 10 * 130; i += 256) {
        int r = i / 130, j = i - r * 130;
        int gy = y0 - 1 + r, gx = x0 - 1 + j;
        float v0 = -1e30f, v1 = -1e30f;          // maxpool pads with -inf
        if ((unsigned)gy < Hn && (unsigned)gx < Wn) {
            int idx = plane + (gy << 8) + gx;
            v0 = x[idx];
            v1 = g_xnew[idx];
        }
        s3[r][j]  = v0;
        sn3[r][j] = v1;
    }
    __syncthreads();

    const int ty = threadIdx.y, tx = threadIdx.x;
    float c0[6], c1[6];
#pragma unroll
    for (int jj = 0; jj < 6; ++jj) {
        int j = 4 * tx + jj;
        c0[jj] = fmaxf(fmaxf(s3[ty][j],  s3[ty + 1][j]),  s3[ty + 2][j]);
        c1[jj] = fmaxf(fmaxf(sn3[ty][j], sn3[ty + 1][j]), sn3[ty + 2][j]);
    }
    float f[4];
#pragma unroll
    for (int i = 0; i < 4; ++i) {
        float m0 = fmaxf(fmaxf(c0[i], c0[i + 1]), c0[i + 2]);
        float m1 = fmaxf(fmaxf(c1[i], c1[i + 1]), c1[i + 2]);
        f[i] = (m0 > THRESH && m1 > THRESH) ? 1.0f : 0.0f;
    }

    const int gy = y0 + ty, gxA = x0 + 4 * tx;
    const int idx = (b << 20) + (gy << 8) + gxA;
#pragma unroll
    for (int c = 0; c < 16; ++c) {
        float4 v = *(const float4*)(g_xnew + idx + (c << 16));
        v.x *= f[0]; v.y *= f[1]; v.z *= f[2]; v.w *= f[3];
        *(float4*)(out + idx + (c << 16)) = v;
    }
}

// ---------------------------------------------------------------------------
extern "C" void kernel_launch(void* const* d_in, const int* in_sizes, int n_in,
                              void* d_out, int out_size)
{
    const float* x  = (const float*)d_in[0];
    // d_in[1] = sobel kernel: fixed by construction, hardcoded
    const float* w1 = (const float*)d_in[2];
    const float* b1 = (const float*)d_in[3];
    const float* w2 = (const float*)d_in[4];
    const unsigned int* um = (const unsigned int*)d_in[5];
    float* out = (float*)d_out;

    const int smem1 = 49152 + 16384 + 1024;   // 66560 B
    cudaFuncSetAttribute(nca_update, cudaFuncAttributeMaxDynamicSharedMemorySize, smem1);

    dim3 g1(Wn / 32, Hn / 8, Bn), tb1(16, 8);
    nca_update<<<g1, tb1, smem1>>>(x, w1, b1, w2, um);

    dim3 g2(Wn / 128, Hn / 8, Bn), tb2(32, 8);
    nca_mask<<<g2, tb2>>>(x, out);
}

// round 7
// speedup vs baseline: 2.5048x; 2.5048x over previous
#include <cuda_runtime.h>

// ---------------------------------------------------------------------------
// NCA step, tensor-core formulation (mma.sync m16n8k8 tf32):
//   p = depthwise [ident, sobel_x, sobel_y]  (16ch -> 48ch)   [scalar, smem]
//   h = relu(W1 p + b1)    GEMM1 [128px x 48] * [48 x 128]    [mma, fp32 acc]
//   dx = W2 h              GEMM2 [128px x 128] * [128 x 16]   [mma, K split 4 warps]
//   x_new = x + dx*mask -> g_xnew ; kernel2 applies alive gating.
// ---------------------------------------------------------------------------

#define Bn 32
#define Cn 16
#define Hn 256
#define Wn 256
#define THRESH 0.1f

__device__ float g_xnew[Bn * Cn * Hn * Wn];

typedef unsigned int u32;

__device__ __forceinline__ u32 f2tf(float f) {
    u32 r; asm("cvt.rna.tf32.f32 %0, %1;" : "=r"(r) : "f"(f)); return r;
}

__device__ __forceinline__ void mma_tf32(float& d0, float& d1, float& d2, float& d3,
                                         u32 a0, u32 a1, u32 a2, u32 a3,
                                         u32 b0, u32 b1) {
    asm volatile("mma.sync.aligned.m16n8k8.row.col.f32.tf32.tf32.f32 "
                 "{%0,%1,%2,%3}, {%4,%5,%6,%7}, {%8,%9}, {%0,%1,%2,%3};"
                 : "+f"(d0), "+f"(d1), "+f"(d2), "+f"(d3)
                 : "r"(a0), "r"(a1), "r"(a2), "r"(a3), "r"(b0), "r"(b1));
}

// smem layout (bytes):
//   [0,      34816) dxs [4][128][17] f32   (xs [16][6][36] f32, 13824 B, overlays start)
//   [34816,  61440) p   [128][52] u32 bits (stride 52 -> conflict-free A-frag loads)
//   [61440,  88064) w1s [128][52] tf32
//   [88064,  96512) w2s [16][132] tf32
//   [96512,  97024) b1s [128] f32
#define SM_P   (34816 / 4)
#define SM_W1  (61440 / 4)
#define SM_W2  (88064 / 4)
#define SM_B1  (96512 / 4)
#define SMEM_BYTES 97024

extern __shared__ u32 sm[];

__global__ void __launch_bounds__(128)
nca_update(const float* __restrict__ x, const float* __restrict__ w1,
           const float* __restrict__ b1, const float* __restrict__ w2,
           const u32* __restrict__ um)
{
    const int tid = threadIdx.x;
    const int b  = blockIdx.z;
    const int y0 = blockIdx.y * 4;
    const int x0 = blockIdx.x * 32;

    float* xs  = (float*)sm;            // [16][6][36], transient
    u32*   ps  = sm + SM_P;             // [128][52]
    u32*   w1s = sm + SM_W1;            // [128][52]
    u32*   w2s = sm + SM_W2;            // [16][132]
    float* b1s = (float*)(sm + SM_B1);  // [128]
    float* dxs = (float*)sm;            // [4][128][17], written after xs is dead

    // ---- load x tile + 1-halo (rows y0-1..y0+4, cols x0-1..x0+32, 16 ch) ----
    const float* xb = x + ((long long)(b * Cn) << 16);
    for (int i = tid; i < 16 * 6 * 34; i += 128) {
        int c = i / 204, rem = i - c * 204;
        int r = rem / 34, col = rem - r * 34;
        int gy = y0 - 1 + r, gx = x0 - 1 + col;
        float v = 0.f;                              // conv 'SAME' zero pad
        if ((unsigned)gy < Hn && (unsigned)gx < Wn) v = xb[(c << 16) + (gy << 8) + gx];
        xs[c * 216 + r * 36 + col] = v;
    }
    __syncthreads();

    // ---- perception: one pixel per thread; p stored as raw f32 bits ----
    // (mma reads them tf32-truncated; ident cols stay exact for the residual)
    const int pr = tid >> 5, pc = tid & 31;
    {
        u32* pp = ps + tid * 52;
#pragma unroll
        for (int c = 0; c < 16; ++c) {
            const float* q = xs + c * 216 + pr * 36 + pc;
            float v00 = q[0],  v01 = q[1],  v02 = q[2];
            float v10 = q[36], v11 = q[37], v12 = q[38];
            float v20 = q[72], v21 = q[73], v22 = q[74];
            float sx = (v02 - v00 + 2.f * (v12 - v10) + v22 - v20) * 0.125f;
            float sy = (v20 - v00 + 2.f * (v21 - v01) + v22 - v02) * 0.125f;
            pp[3 * c + 0] = __float_as_uint(v11);
            pp[3 * c + 1] = __float_as_uint(sx);
            pp[3 * c + 2] = __float_as_uint(sy);
        }
    }
    // ---- stage weights (rna-rounded tf32) ----
    for (int i = tid; i < 6144; i += 128) {        // w1 [128][48] row-major
        int n = i / 48, k = i - n * 48;
        w1s[n * 52 + k] = f2tf(w1[i]);
    }
    for (int i = tid; i < 2048; i += 128) {        // w2 [16][128] row-major
        int n = i >> 7, k = i & 127;
        w2s[n * 132 + k] = f2tf(w2[i]);
    }
    b1s[tid] = b1[tid];
    __syncthreads();

    const int lane = tid & 31, wid = tid >> 5;
    const int g = lane >> 2, tig = lane & 3;
    const int wb = wid * 32;                       // this warp's hidden-col base

    // B1 fragments: B[k][n] = w1[n][k]; b0=(row k=tig, col n=g), b1 k+4
    u32 bf[6][4][2];
#pragma unroll
    for (int kt = 0; kt < 6; ++kt)
#pragma unroll
        for (int nn = 0; nn < 4; ++nn) {
            int n = wb + nn * 8 + g;
            bf[kt][nn][0] = w1s[n * 52 + kt * 8 + tig];
            bf[kt][nn][1] = w1s[n * 52 + kt * 8 + tig + 4];
        }
    // B2 fragments: B[k=hcol][n=ch] = w2[ch][hcol], K local to this warp
    u32 b2f[4][2][2];
#pragma unroll
    for (int kk = 0; kk < 4; ++kk)
#pragma unroll
        for (int n2 = 0; n2 < 2; ++n2) {
            int n = n2 * 8 + g;
            b2f[kk][n2][0] = w2s[n * 132 + wb + kk * 8 + tig];
            b2f[kk][n2][1] = w2s[n * 132 + wb + kk * 8 + tig + 4];
        }
    // bias for D1 init: D cols are hidden units; c0 col = 2*tig, c1 = +1
    float bs[4][2];
#pragma unroll
    for (int nn = 0; nn < 4; ++nn) {
        int n = wb + nn * 8 + 2 * tig;
        bs[nn][0] = b1s[n];
        bs[nn][1] = b1s[n + 1];
    }

    // mask (early, hides LDG latency behind the mma loop)
    const int gy = y0 + pr, gx = x0 + pc;
    const float mfl = um[(b << 16) + (gy << 8) + gx] ? 1.f : 0.f;

    const int srcA = (lane & ~3) | (tig >> 1);     // D->A transpose shuffle sources
    const int srcB = srcA + 2;
    const bool odd = (tig & 1);

#pragma unroll 1
    for (int m = 0; m < 8; ++m) {                  // 8 m-tiles of 16 pixels
        // A1 fragments from p: a0=(row g, col tig), a1 row+8, a2 col+4, a3 both
        u32 af[6][4];
        const u32* prow0 = ps + (m * 16 + g) * 52;
        const u32* prow1 = prow0 + 8 * 52;
#pragma unroll
        for (int kt = 0; kt < 6; ++kt) {
            af[kt][0] = prow0[kt * 8 + tig];
            af[kt][1] = prow1[kt * 8 + tig];
            af[kt][2] = prow0[kt * 8 + tig + 4];
            af[kt][3] = prow1[kt * 8 + tig + 4];
        }
        float dq0[4] = {0.f, 0.f, 0.f, 0.f};       // GEMM2 acc, ch 0..7
        float dq1[4] = {0.f, 0.f, 0.f, 0.f};       // GEMM2 acc, ch 8..15
#pragma unroll
        for (int nn = 0; nn < 4; ++nn) {           // hidden n-tile == GEMM2 k-chunk
            float d0 = bs[nn][0], d1 = bs[nn][1], d2 = bs[nn][0], d3 = bs[nn][1];
#pragma unroll
            for (int kt = 0; kt < 6; ++kt)
                mma_tf32(d0, d1, d2, d3,
                         af[kt][0], af[kt][1], af[kt][2], af[kt][3],
                         bf[kt][nn][0], bf[kt][nn][1]);
            d0 = fmaxf(d0, 0.f); d1 = fmaxf(d1, 0.f);
            d2 = fmaxf(d2, 0.f); d3 = fmaxf(d3, 0.f);
            // D-frag (cols 2t,2t+1) -> A-frag (cols t, t+4) via shuffles
            float t0 = __shfl_sync(0xffffffffu, d0, srcA);
            float t1 = __shfl_sync(0xffffffffu, d1, srcA);
            float t2 = __shfl_sync(0xffffffffu, d2, srcA);
            float t3 = __shfl_sync(0xffffffffu, d3, srcA);
            float u0 = __shfl_sync(0xffffffffu, d0, srcB);
            float u1 = __shfl_sync(0xffffffffu, d1, srcB);
            float u2 = __shfl_sync(0xffffffffu, d2, srcB);
            float u3 = __shfl_sync(0xffffffffu, d3, srcB);
            u32 a0 = __float_as_uint(odd ? t1 : t0);
            u32 a1 = __float_as_uint(odd ? t3 : t2);
            u32 a2 = __float_as_uint(odd ? u1 : u0);
            u32 a3 = __float_as_uint(odd ? u3 : u2);
            mma_tf32(dq0[0], dq0[1], dq0[2], dq0[3], a0, a1, a2, a3,
                     b2f[nn][0][0], b2f[nn][0][1]);
            mma_tf32(dq1[0], dq1[1], dq1[2], dq1[3], a0, a1, a2, a3,
                     b2f[nn][1][0], b2f[nn][1][1]);
        }
        // stage this warp's partial dx (its 32 hidden cols) for the m-tile
        float* dst  = dxs + wid * 2176 + (m * 16 + g) * 17;
        float* dst2 = dst + 8 * 17;
        dst[2 * tig]      = dq0[0];  dst[2 * tig + 1]      = dq0[1];
        dst[8 + 2 * tig]  = dq1[0];  dst[8 + 2 * tig + 1]  = dq1[1];
        dst2[2 * tig]     = dq0[2];  dst2[2 * tig + 1]     = dq0[3];
        dst2[8 + 2 * tig] = dq1[2];  dst2[8 + 2 * tig + 1] = dq1[3];
    }
    __syncthreads();

    // ---- reduce the 4 warp partials, apply mask + residual, write x_new ----
    const u32* pp = ps + tid * 52;
    const int obase = (b << 20) + (gy << 8) + gx;
#pragma unroll
    for (int ch = 0; ch < 16; ++ch) {
        float s = dxs[0 * 2176 + tid * 17 + ch] + dxs[1 * 2176 + tid * 17 + ch]
                + dxs[2 * 2176 + tid * 17 + ch] + dxs[3 * 2176 + tid * 17 + ch];
        float xv = __uint_as_float(pp[3 * ch]);    // exact x (ident channel)
        g_xnew[obase + (ch << 16)] = xv + s * mfl;
    }
}

// ---------------------------------------------------------------------------
// Kernel 2: alive gating.  out = x_new * (maxpool3(x[3])>thr & maxpool3(x_new[3])>thr)
// ---------------------------------------------------------------------------
__global__ void __launch_bounds__(256)
nca_mask(const float* __restrict__ x, float* __restrict__ out)
{
    __shared__ float s3[10][136];
    __shared__ float sn3[10][136];

    const int b  = blockIdx.z;
    const int y0 = blockIdx.y * 8;
    const int x0 = blockIdx.x * 128;
    const int tid = threadIdx.y * 32 + threadIdx.x;
    const int plane = ((b * Cn + 3) << 16);

    for (int i = tid; i < 10 * 130; i += 256) {
        int r = i / 130, j = i - r * 130;
        int gy = y0 - 1 + r, gx = x0 - 1 + j;
        float v0 = -1e30f, v1 = -1e30f;
        if ((unsigned)gy < Hn && (unsigned)gx < Wn) {
            int idx = plane + (gy << 8) + gx;
            v0 = x[idx];
            v1 = g_xnew[idx];
        }
        s3[r][j]  = v0;
        sn3[r][j] = v1;
    }
    __syncthreads();

    const int ty = threadIdx.y, tx = threadIdx.x;
    float c0[6], c1[6];
#pragma unroll
    for (int jj = 0; jj < 6; ++jj) {
        int j = 4 * tx + jj;
        c0[jj] = fmaxf(fmaxf(s3[ty][j],  s3[ty + 1][j]),  s3[ty + 2][j]);
        c1[jj] = fmaxf(fmaxf(sn3[ty][j], sn3[ty + 1][j]), sn3[ty + 2][j]);
    }
    float f[4];
#pragma unroll
    for (int i = 0; i < 4; ++i) {
        float m0 = fmaxf(fmaxf(c0[i], c0[i + 1]), c0[i + 2]);
        float m1 = fmaxf(fmaxf(c1[i], c1[i + 1]), c1[i + 2]);
        f[i] = (m0 > THRESH && m1 > THRESH) ? 1.0f : 0.0f;
    }

    const int gy = y0 + ty, gxA = x0 + 4 * tx;
    const int idx = (b << 20) + (gy << 8) + gxA;
#pragma unroll
    for (int c = 0; c < 16; ++c) {
        float4 v = *(const float4*)(g_xnew + idx + (c << 16));
        v.x *= f[0]; v.y *= f[1]; v.z *= f[2]; v.w *= f[3];
        *(float4*)(out + idx + (c << 16)) = v;
    }
}

// ---------------------------------------------------------------------------
extern "C" void kernel_launch(void* const* d_in, const int* in_sizes, int n_in,
                              void* d_out, int out_size)
{
    const float* x  = (const float*)d_in[0];
    // d_in[1] = sobel kernel: fixed by construction, hardcoded in perception
    const float* w1 = (const float*)d_in[2];
    const float* b1 = (const float*)d_in[3];
    const float* w2 = (const float*)d_in[4];
    const u32*   um = (const u32*)d_in[5];
    float* out = (float*)d_out;

    cudaFuncSetAttribute(nca_update, cudaFuncAttributeMaxDynamicSharedMemorySize, SMEM_BYTES);

    dim3 g1(Wn / 32, Hn / 4, Bn);
    nca_update<<<g1, 128, SMEM_BYTES>>>(x, w1, b1, w2, um);

    dim3 g2(Wn / 128, Hn / 8, Bn), tb2(32, 8);
    nca_mask<<<g2, tb2>>>(x, out);
}